// round 3
// baseline (speedup 1.0000x reference)
#include <cuda_runtime.h>

#define BB 2
#define HH 16
#define SS 2048
#define DD 64
#define TQ 16
#define TK 64
#define KPAD 68            // row stride in floats: 17 float4s == 1 (mod 8) -> conflict-free LDS.128
#define NTHREADS 256
#define CTX_ELEMS (BB*HH*SS*DD)
#define MASK_ELEMS (BB*SS*SS)
#define SMEM_FLOATS (TQ*SS + TK*KPAD + TQ*DD)
#define SMEM_BYTES (SMEM_FLOATS * 4)

// Canonical mask scratch (uint8, 1 = masked) + dtype-detection flags
__device__ unsigned char g_mask[MASK_ELEMS];
__device__ unsigned int g_not01;    // saw a word not in {0,1}
__device__ unsigned int g_notf32;   // saw a word not in {0, 0x3F800000}

// ---- Kernel A: sample mask buffer as u32 words, classify dtype ----
__global__ void detect_mask_kernel(const unsigned int* __restrict__ m)
{
    if (threadIdx.x == 0) { g_not01 = 0; g_notf32 = 0; }
    __syncthreads();
    unsigned int n01 = 0, nf = 0;
    // sample 16384 words (64KB) — overwhelming statistics for 0/1 random mask
    for (int i = threadIdx.x; i < 16384; i += blockDim.x) {
        unsigned int w = m[i];
        if (w > 1u) n01 = 1u;
        if (w != 0u && w != 0x3F800000u) nf = 1u;
    }
    if (n01) atomicOr(&g_not01, 1u);
    if (nf)  atomicOr(&g_notf32, 1u);
}

// ---- Kernel B: canonicalize mask into g_mask as uint8 ----
__global__ void convert_mask_kernel(const void* __restrict__ mraw)
{
    // type: not01==0 -> int32; else notf32==0 -> float32; else uint8
    const unsigned int not01 = g_not01, notf32 = g_notf32;
    const int total = MASK_ELEMS;
    for (int i = blockIdx.x * blockDim.x + threadIdx.x; i < total;
         i += gridDim.x * blockDim.x) {
        unsigned char v;
        if (!not01) {
            v = (((const int*)mraw)[i] != 0);
        } else if (!notf32) {
            v = (((const float*)mraw)[i] != 0.0f);
        } else {
            v = (((const unsigned char*)mraw)[i] != 0);
        }
        g_mask[i] = v;
    }
}

__global__ __launch_bounds__(NTHREADS, 1)
void attn_kernel(const float* __restrict__ Qp, const float* __restrict__ Kp,
                 const float* __restrict__ Vp, float* __restrict__ out)
{
    extern __shared__ float smem[];
    float* sS = smem;                       // TQ x SS scores (then exp values)
    float* sK = sS + TQ * SS;               // TK x KPAD streaming K/V tile
    float* sQ = sK + TK * KPAD;             // TQ x DD Q tile; reused as sInv[TQ] later

    const int qblocks = SS / TQ;            // 128
    const int head = blockIdx.x / qblocks;  // 0..31 (= b*HH + h)
    const int qblk = blockIdx.x % qblocks;
    const int b    = head / HH;
    const int q0   = qblk * TQ;

    const float* Qh = Qp + (size_t)head * SS * DD;
    const float* Kh = Kp + (size_t)head * SS * DD;
    const float* Vh = Vp + (size_t)head * SS * DD;
    const unsigned char* Mh = g_mask + (size_t)b * SS * SS;
    float* ctx_out = out + (size_t)head * SS * DD;
    float* att_out = out + (size_t)CTX_ELEMS + (size_t)head * SS * SS;

    const int tid  = threadIdx.x;
    const int warp = tid >> 5;
    const int lane = tid & 31;

    // ---- Load Q tile: TQ*DD = 1024 floats = 256 float4, one per thread ----
    ((float4*)sQ)[tid] = ((const float4*)(Qh + (size_t)q0 * DD))[tid];

    // ---- Phase 1: scores S = scale*Q.K^T with mask, into sS ----
    const int qa = warp * 2;                       // this warp owns rows qa, qa+1
    float* sRow0 = sS + (size_t)qa * SS;
    float* sRow1 = sS + (size_t)(qa + 1) * SS;
    const unsigned char* mRow0 = Mh + (size_t)(q0 + qa) * SS;
    const unsigned char* mRow1 = mRow0 + SS;

    for (int kt = 0; kt < SS; kt += TK) {
        __syncthreads();   // protect sK from previous iteration's readers
        // load K chunk [TK x DD]: 1024 float4, 4 per thread
        #pragma unroll
        for (int i = 0; i < 4; i++) {
            int idx = tid + i * NTHREADS;
            int r = idx >> 4;                       // 16 float4 per row
            int c = idx & 15;
            ((float4*)(sK + r * KPAD))[c] =
                ((const float4*)(Kh + (size_t)(kt + r) * DD))[c];
        }
        __syncthreads();

        float a00 = 0.f, a01 = 0.f, a10 = 0.f, a11 = 0.f;
        const float* q0p = sQ + qa * DD;
        const float* q1p = q0p + DD;
        const float* k0p = sK + lane * KPAD;
        const float* k1p = sK + (lane + 32) * KPAD;
        #pragma unroll
        for (int d = 0; d < DD; d += 4) {
            float4 qv0 = *(const float4*)(q0p + d);
            float4 qv1 = *(const float4*)(q1p + d);
            float4 kv0 = *(const float4*)(k0p + d);
            float4 kv1 = *(const float4*)(k1p + d);
            a00 += qv0.x*kv0.x + qv0.y*kv0.y + qv0.z*kv0.z + qv0.w*kv0.w;
            a01 += qv0.x*kv1.x + qv0.y*kv1.y + qv0.z*kv1.z + qv0.w*kv1.w;
            a10 += qv1.x*kv0.x + qv1.y*kv0.y + qv1.z*kv0.z + qv1.w*kv0.w;
            a11 += qv1.x*kv1.x + qv1.y*kv1.y + qv1.z*kv1.z + qv1.w*kv1.w;
        }
        const int kA = kt + lane;
        const int kB = kt + lane + 32;
        // reference: scores*scale, then where(mask, -1e9, .)
        sRow0[kA] = mRow0[kA] ? -1e9f : a00 * 0.125f;
        sRow0[kB] = mRow0[kB] ? -1e9f : a01 * 0.125f;
        sRow1[kA] = mRow1[kA] ? -1e9f : a10 * 0.125f;
        sRow1[kB] = mRow1[kB] ? -1e9f : a11 * 0.125f;
    }
    __syncthreads();

    // ---- Phase 2: per-row softmax; keep e in sS, write normalized probs to gmem ----
    float* sInv = sQ;   // Q tile no longer needed
    #pragma unroll
    for (int rr = 0; rr < 2; rr++) {
        const int r = qa + rr;
        float* row = sS + (size_t)r * SS;
        float m = -3.4e38f;
        for (int i = lane; i < SS; i += 32) m = fmaxf(m, row[i]);
        #pragma unroll
        for (int o = 16; o; o >>= 1) m = fmaxf(m, __shfl_xor_sync(0xFFFFFFFFu, m, o));
        float sum = 0.f;
        for (int i = lane; i < SS; i += 32) {
            float e = __expf(row[i] - m);   // masked (-1e9) -> 0, matching reference
            row[i] = e;
            sum += e;
        }
        #pragma unroll
        for (int o = 16; o; o >>= 1) sum += __shfl_xor_sync(0xFFFFFFFFu, sum, o);
        const float inv = 1.0f / sum;
        if (lane == 0) sInv[r] = inv;

        float4* dst = (float4*)(att_out + (size_t)(q0 + r) * SS);
        const float4* src = (const float4*)row;
        for (int i = lane; i < SS / 4; i += 32) {
            float4 v = src[i];
            v.x *= inv; v.y *= inv; v.z *= inv; v.w *= inv;
            dst[i] = v;
        }
    }
    __syncthreads();

    // ---- Phase 3: context = (e @ V) * inv ----
    const int q  = tid >> 4;                 // 0..15
    const int d4 = (tid & 15) * 4;           // 0,4,...,60
    float ax = 0.f, ay = 0.f, az = 0.f, aw = 0.f;
    const float* prow = sS + (size_t)q * SS;

    for (int kt = 0; kt < SS; kt += TK) {
        __syncthreads();   // protect sK tile reuse
        #pragma unroll
        for (int i = 0; i < 4; i++) {
            int idx = tid + i * NTHREADS;
            int r = idx >> 4;
            int c = idx & 15;
            ((float4*)(sK + r * KPAD))[c] =
                ((const float4*)(Vh + (size_t)(kt + r) * DD))[c];
        }
        __syncthreads();

        #pragma unroll
        for (int kk = 0; kk < TK; kk += 4) {
            float4 p = *(const float4*)(prow + kt + kk);
            const float* vb = sK + kk * KPAD + d4;
            float4 v0 = *(const float4*)(vb);
            float4 v1 = *(const float4*)(vb + KPAD);
            float4 v2 = *(const float4*)(vb + 2 * KPAD);
            float4 v3 = *(const float4*)(vb + 3 * KPAD);
            ax += p.x*v0.x + p.y*v1.x + p.z*v2.x + p.w*v3.x;
            ay += p.x*v0.y + p.y*v1.y + p.z*v2.y + p.w*v3.y;
            az += p.x*v0.z + p.y*v1.z + p.z*v2.z + p.w*v3.z;
            aw += p.x*v0.w + p.y*v1.w + p.z*v2.w + p.w*v3.w;
        }
    }

    const float inv = sInv[q];
    float4 res;
    res.x = ax * inv; res.y = ay * inv; res.z = az * inv; res.w = aw * inv;
    *(float4*)(ctx_out + (size_t)(q0 + q) * DD + d4) = res;
}

extern "C" void kernel_launch(void* const* d_in, const int* in_sizes, int n_in,
                              void* d_out, int out_size)
{
    (void)in_sizes; (void)n_in; (void)out_size;
    const float* Q = (const float*)d_in[0];
    const float* K = (const float*)d_in[1];
    const float* V = (const float*)d_in[2];
    const void*  M = d_in[3];
    // d_in[4] (dim_key) unused: DD=64 compile-time
    float* out = (float*)d_out;

    cudaFuncSetAttribute(attn_kernel,
                         cudaFuncAttributeMaxDynamicSharedMemorySize, SMEM_BYTES);

    // 1) classify mask dtype, 2) canonicalize to uint8 in g_mask
    detect_mask_kernel<<<1, 256>>>((const unsigned int*)M);
    convert_mask_kernel<<<4096, 1024>>>(M);

    dim3 grid(BB * HH * (SS / TQ));   // 4096 CTAs
    dim3 block(NTHREADS);
    attn_kernel<<<grid, block, SMEM_BYTES>>>(Q, K, V, out);
}